// round 7
// baseline (speedup 1.0000x reference)
#include <cuda_runtime.h>

// Problem constants (fixed by the dataset)
#define BATCH 8192
#define HDIM  512
#define DPTH  16
#define WPB   8                 // warps per block
#define NBLK  (BATCH / WPB)     // 1024 CTAs

// Scratch (__device__ globals per allocation rules). g_done starts 0 and is
// reset by the last CTA each launch -> clean state for every graph replay.
__device__ float g_partial[NBLK];
__device__ unsigned int g_done;

// Warp-per-sample streaming kernel + fused deterministic reduction.
// Each warp: hidden[b] in registers, stream 16 weight rows (2 at a time,
// 8 LDG.128 in flight), transposed cross-lane tree reduction so lane l holds
// the logit for d = l & 15, per-lane BCE, per-warp loss. CTA partial summed
// in fixed order; last CTA (release-atomic ticket, fence-free) reduces the
// 1024 partials in fixed index order -> bitwise-deterministic mean.
__global__ __launch_bounds__(256) void hs_fused_kernel(
    const float* __restrict__ hidden,     // [BATCH, HDIM]
    const int*   __restrict__ target,     // [BATCH]
    const float* __restrict__ weights,    // [V, DPTH, HDIM]
    const float* __restrict__ codes,      // [V, DPTH]
    const int*   __restrict__ lengths,    // [V]
    float*       __restrict__ out)        // [1]
{
    const int tid  = threadIdx.x;
    const int warp = tid >> 5;
    const int lane = tid & 31;
    const int b    = blockIdx.x * WPB + warp;

    const int word = target[b];           // broadcast load

    // Hoist the epilogue operands so their latency hides under the stream.
    const int   L = lengths[word];
    const float t = codes[(size_t)word * DPTH + (lane & 15)];

    // hidden[b]: lane takes float4 {lane, lane+32, lane+64, lane+96}
    const float4* hp = reinterpret_cast<const float4*>(hidden + (size_t)b * HDIM);
    float4 h[4];
    #pragma unroll
    for (int i = 0; i < 4; i++) h[i] = hp[lane + 32 * i];

    const float4* wp =
        reinterpret_cast<const float4*>(weights + (size_t)word * DPTH * HDIM);

    float acc[DPTH];
    #pragma unroll
    for (int d = 0; d < DPTH; d += 2) {
        float4 a[4], c[4];
        #pragma unroll
        for (int i = 0; i < 4; i++) a[i] = wp[(size_t)d * 128 + lane + 32 * i];
        #pragma unroll
        for (int i = 0; i < 4; i++) c[i] = wp[(size_t)(d + 1) * 128 + lane + 32 * i];
        float s0 = 0.0f, s1 = 0.0f;
        #pragma unroll
        for (int i = 0; i < 4; i++) {
            s0 += a[i].x * h[i].x + a[i].y * h[i].y + a[i].z * h[i].z + a[i].w * h[i].w;
            s1 += c[i].x * h[i].x + c[i].y * h[i].y + c[i].z * h[i].z + c[i].w * h[i].w;
        }
        acc[d]     = s0;
        acc[d + 1] = s1;
    }

    // ---- Transposed cross-lane reduction ----
    #pragma unroll
    for (int i = 0; i < 16; i++)
        acc[i] += __shfl_xor_sync(0xffffffff, acc[i], 16);
    #pragma unroll
    for (int i = 0; i < 8; i++) {
        const bool hi = (lane & 8);
        float send = hi ? acc[i] : acc[i + 8];
        float o = __shfl_xor_sync(0xffffffff, send, 8);
        acc[i] = (hi ? acc[i + 8] : acc[i]) + o;
    }
    #pragma unroll
    for (int i = 0; i < 4; i++) {
        const bool hi = (lane & 4);
        float send = hi ? acc[i] : acc[i + 4];
        float o = __shfl_xor_sync(0xffffffff, send, 4);
        acc[i] = (hi ? acc[i + 4] : acc[i]) + o;
    }
    #pragma unroll
    for (int i = 0; i < 2; i++) {
        const bool hi = (lane & 2);
        float send = hi ? acc[i] : acc[i + 2];
        float o = __shfl_xor_sync(0xffffffff, send, 2);
        acc[i] = (hi ? acc[i + 2] : acc[i]) + o;
    }
    {
        const bool hi = (lane & 1);
        float send = hi ? acc[0] : acc[1];
        float o = __shfl_xor_sync(0xffffffff, send, 1);
        acc[0] = (hi ? acc[1] : acc[0]) + o;
    }

    // ---- BCE-with-logits: lane l handles path node d = l & 15 ----
    const int   d = lane & 15;
    const float x = acc[0];
    float bce = fmaxf(x, 0.0f) - x * t + log1pf(expf(-fabsf(x)));
    float v   = (d < L) ? bce : 0.0f;
    #pragma unroll
    for (int o = 8; o; o >>= 1)       // sum within each 16-lane half
        v += __shfl_xor_sync(0xffffffff, v, o);

    // ---- Fused reduction ----
    __shared__ float sloss[WPB];
    __shared__ float sred[WPB];
    __shared__ bool  is_last;
    if (lane == 0) sloss[warp] = v / (float)L;
    __syncthreads();

    if (warp == 0) {
        float p = (lane < WPB) ? sloss[lane] : 0.0f;
        #pragma unroll
        for (int o = 4; o; o >>= 1)   // fixed-order tree over 8 values
            p += __shfl_xor_sync(0xffffffff, p, o);
        if (lane == 0) {
            // L2 store + release atomic from the SAME thread: orders the
            // store without any L1-flushing fence.
            asm volatile("st.global.cg.f32 [%0], %1;"
                         :: "l"(&g_partial[blockIdx.x]), "f"(p) : "memory");
            unsigned int tk;
            asm volatile("atom.release.gpu.global.add.u32 %0, [%1], %2;"
                         : "=r"(tk) : "l"(&g_done), "r"(1u) : "memory");
            is_last = (tk == NBLK - 1);
        }
    }
    __syncthreads();
    if (!is_last) return;

    // Last CTA: all other partials are release-ordered into L2 before our
    // ticket read. Fixed-order reduction of the 1024 CTA partials.
    if (tid == 0) g_done = 0;         // reset for next graph replay

    float acc2 = 0.0f;
    #pragma unroll
    for (int i = 0; i < NBLK / 256; i++)      // 4 values per thread
        acc2 += __ldcg(&g_partial[tid + 256 * i]);
    #pragma unroll
    for (int o = 16; o; o >>= 1)
        acc2 += __shfl_xor_sync(0xffffffff, acc2, o);
    if (lane == 0) sred[warp] = acc2;
    __syncthreads();
    if (warp == 0) {
        float s = (lane < WPB) ? sred[lane] : 0.0f;
        #pragma unroll
        for (int o = 4; o; o >>= 1)
            s += __shfl_xor_sync(0xffffffff, s, o);
        if (lane == 0) out[0] = s / (float)BATCH;
    }
}

extern "C" void kernel_launch(void* const* d_in, const int* in_sizes, int n_in,
                              void* d_out, int out_size)
{
    const float* hidden  = (const float*)d_in[0];
    const int*   target  = (const int*)  d_in[1];
    const float* weights = (const float*)d_in[2];
    const float* codes   = (const float*)d_in[3];
    const int*   lengths = (const int*)  d_in[4];
    float* out = (float*)d_out;

    hs_fused_kernel<<<NBLK, 256>>>(hidden, target, weights, codes, lengths, out);
}

// round 8
// speedup vs baseline: 1.0338x; 1.0338x over previous
#include <cuda_runtime.h>

// Problem constants (fixed by the dataset)
#define BATCH 8192
#define HDIM  512
#define DPTH  16
#define WPB   8                 // warps per block
#define NBLK  (BATCH / WPB)     // 1024 CTAs

// Scratch (__device__ globals per allocation rules). g_done starts 0 and is
// reset by the last CTA each launch -> clean state for every graph replay.
__device__ float g_partial[NBLK];
__device__ unsigned int g_done;

// Warp-per-sample streaming kernel + fused deterministic reduction.
// Main body is IDENTICAL to the proven 39.3us R6 kernel (codes/lengths loaded
// in the epilogue, NOT hoisted -- hoisting cost 18 registers and ~5us in R7).
// Tail: per-warp loss -> smem -> fixed-order CTA partial -> release-atomic
// ticket (fence-free) -> last CTA reduces 1024 partials in fixed index order.
__global__ __launch_bounds__(256) void hs_fused_kernel(
    const float* __restrict__ hidden,     // [BATCH, HDIM]
    const int*   __restrict__ target,     // [BATCH]
    const float* __restrict__ weights,    // [V, DPTH, HDIM]
    const float* __restrict__ codes,      // [V, DPTH]
    const int*   __restrict__ lengths,    // [V]
    float*       __restrict__ out)        // [1]
{
    const int tid  = threadIdx.x;
    const int warp = tid >> 5;
    const int lane = tid & 31;
    const int b    = blockIdx.x * WPB + warp;

    const int word = target[b];           // broadcast load

    // hidden[b]: lane takes float4 {lane, lane+32, lane+64, lane+96}
    const float4* hp = reinterpret_cast<const float4*>(hidden + (size_t)b * HDIM);
    float4 h[4];
    #pragma unroll
    for (int i = 0; i < 4; i++) h[i] = hp[lane + 32 * i];

    const float4* wp =
        reinterpret_cast<const float4*>(weights + (size_t)word * DPTH * HDIM);

    float acc[DPTH];
    #pragma unroll
    for (int d = 0; d < DPTH; d += 2) {
        float4 a[4], c[4];
        #pragma unroll
        for (int i = 0; i < 4; i++) a[i] = wp[(size_t)d * 128 + lane + 32 * i];
        #pragma unroll
        for (int i = 0; i < 4; i++) c[i] = wp[(size_t)(d + 1) * 128 + lane + 32 * i];
        float s0 = 0.0f, s1 = 0.0f;
        #pragma unroll
        for (int i = 0; i < 4; i++) {
            s0 += a[i].x * h[i].x + a[i].y * h[i].y + a[i].z * h[i].z + a[i].w * h[i].w;
            s1 += c[i].x * h[i].x + c[i].y * h[i].y + c[i].z * h[i].z + c[i].w * h[i].w;
        }
        acc[d]     = s0;
        acc[d + 1] = s1;
    }

    // ---- Transposed cross-lane reduction: lane l ends with logit d = l & 15
    #pragma unroll
    for (int i = 0; i < 16; i++)
        acc[i] += __shfl_xor_sync(0xffffffff, acc[i], 16);
    #pragma unroll
    for (int i = 0; i < 8; i++) {
        const bool hi = (lane & 8);
        float send = hi ? acc[i] : acc[i + 8];
        float o = __shfl_xor_sync(0xffffffff, send, 8);
        acc[i] = (hi ? acc[i + 8] : acc[i]) + o;
    }
    #pragma unroll
    for (int i = 0; i < 4; i++) {
        const bool hi = (lane & 4);
        float send = hi ? acc[i] : acc[i + 4];
        float o = __shfl_xor_sync(0xffffffff, send, 4);
        acc[i] = (hi ? acc[i + 4] : acc[i]) + o;
    }
    #pragma unroll
    for (int i = 0; i < 2; i++) {
        const bool hi = (lane & 2);
        float send = hi ? acc[i] : acc[i + 2];
        float o = __shfl_xor_sync(0xffffffff, send, 2);
        acc[i] = (hi ? acc[i + 2] : acc[i]) + o;
    }
    {
        const bool hi = (lane & 1);
        float send = hi ? acc[0] : acc[1];
        float o = __shfl_xor_sync(0xffffffff, send, 1);
        acc[0] = (hi ? acc[1] : acc[0]) + o;
    }

    // ---- BCE-with-logits (epilogue loads, as in the 39.3us body) ----
    const int   d = lane & 15;
    const float x = acc[0];
    const float t = codes[(size_t)word * DPTH + d];   // 64B line, bcast halves
    const int   L = lengths[word];
    float bce = fmaxf(x, 0.0f) - x * t + log1pf(expf(-fabsf(x)));
    float v   = (d < L) ? bce : 0.0f;
    #pragma unroll
    for (int o = 8; o; o >>= 1)       // sum within each 16-lane half
        v += __shfl_xor_sync(0xffffffff, v, o);

    // ---- Fused reduction ----
    __shared__ float sloss[WPB];
    __shared__ float sred[WPB];
    __shared__ bool  is_last;
    if (lane == 0) sloss[warp] = v / (float)L;
    __syncthreads();

    if (warp == 0) {
        float p = (lane < WPB) ? sloss[lane] : 0.0f;
        #pragma unroll
        for (int o = 4; o; o >>= 1)   // fixed-order tree over 8 values
            p += __shfl_xor_sync(0xffffffff, p, o);
        if (lane == 0) {
            // L2 store + release atomic from the SAME thread: orders the
            // store without any L1-flushing fence.
            asm volatile("st.global.cg.f32 [%0], %1;"
                         :: "l"(&g_partial[blockIdx.x]), "f"(p) : "memory");
            unsigned int tk;
            asm volatile("atom.release.gpu.global.add.u32 %0, [%1], %2;"
                         : "=r"(tk) : "l"(&g_done), "r"(1u) : "memory");
            is_last = (tk == NBLK - 1);
        }
    }
    __syncthreads();
    if (!is_last) return;

    // Last CTA: all other partials are release-ordered into L2 before our
    // ticket read. Fixed-order reduction -> bitwise-deterministic mean.
    if (tid == 0) g_done = 0;         // reset for next graph replay

    float acc2 = 0.0f;
    #pragma unroll
    for (int i = 0; i < NBLK / 256; i++)      // 4 values per thread
        acc2 += __ldcg(&g_partial[tid + 256 * i]);
    #pragma unroll
    for (int o = 16; o; o >>= 1)
        acc2 += __shfl_xor_sync(0xffffffff, acc2, o);
    if (lane == 0) sred[warp] = acc2;
    __syncthreads();
    if (warp == 0) {
        float s = (lane < WPB) ? sred[lane] : 0.0f;
        #pragma unroll
        for (int o = 4; o; o >>= 1)
            s += __shfl_xor_sync(0xffffffff, s, o);
        if (lane == 0) out[0] = s / (float)BATCH;
    }
}

extern "C" void kernel_launch(void* const* d_in, const int* in_sizes, int n_in,
                              void* d_out, int out_size)
{
    const float* hidden  = (const float*)d_in[0];
    const int*   target  = (const int*)  d_in[1];
    const float* weights = (const float*)d_in[2];
    const float* codes   = (const float*)d_in[3];
    const int*   lengths = (const int*)  d_in[4];
    float* out = (float*)d_out;

    hs_fused_kernel<<<NBLK, 256>>>(hidden, target, weights, codes, lengths, out);
}